// round 3
// baseline (speedup 1.0000x reference)
#include <cuda_runtime.h>

// Problem constants
#define S    8192
#define D    768
#define D4   (D/4)        // 192 float4 per row
#define NA   256
#define NO   256
#define NP   (NA*NO)      // 65536 pairs
#define NCAT 13
#define NPOL 3
#define NK   18           // 2 valid + 13 cat + 3 pol partials per span

// Output layout (flattened tuple, fp32)
#define OFF_AID ((size_t)NP * (2*D))
#define OFF_OID (OFF_AID + NP)
#define OFF_CAT (OFF_OID + NP)
#define OFF_POL (OFF_CAT + (size_t)NP*NCAT)
#define OFF_MSK (OFF_POL + (size_t)NP*NPOL)

// Scratch (allocation-free rule: device globals)
__device__ float g_rep[(NA+NO)*D];     // aspect rows [0,256), opinion rows [256,512)
__device__ float g_part[(NA+NO)*NK];   // per-span partial logits
__device__ float g_mask[NP];           // 1.0 / 0.0 per pair

static __device__ __forceinline__ void vmax(float4& a, const float4 b) {
    a.x = fmaxf(a.x, b.x);
    a.y = fmaxf(a.y, b.y);
    a.z = fmaxf(a.z, b.z);
    a.w = fmaxf(a.w, b.w);
}

// ---------------------------------------------------------------------------
// Kernel A (fused pool + partial logits). One block per span, 192 threads.
// Max-pool with 4 independent accumulators (MLP=4; max is exactly
// associative so result is bit-identical to the serial version), then the
// same deterministic per-span partial-logit reduction as before.
// ---------------------------------------------------------------------------
__global__ void __launch_bounds__(192) pool_part_kernel(
    const float* __restrict__ word_rep,
    const int*   __restrict__ aspects,
    const int*   __restrict__ opinions,
    const float* __restrict__ Wv,   // (2D, 2)
    const float* __restrict__ Wc,   // (2D, 13)
    const float* __restrict__ Wp)   // (2D, 3)
{
    int s = blockIdx.x;                       // 0..511
    const int* sp = (s < NA) ? (aspects + 2*s) : (opinions + 2*(s - NA));
    int head = sp[0];
    int w    = sp[1] - head;                  // 1..40
    int c = threadIdx.x;                      // float4 lane 0..191

    const float4* base = (const float4*)word_rep + (size_t)head * D4 + c;
    float4 m0 = base[0];
    float4 m1 = m0, m2 = m0, m3 = m0;         // duplicates are max-identity
    int k = 1;
    for (; k + 3 < w; k += 4) {
        float4 a0 = base[(size_t)(k+0) * D4];
        float4 a1 = base[(size_t)(k+1) * D4];
        float4 a2 = base[(size_t)(k+2) * D4];
        float4 a3 = base[(size_t)(k+3) * D4];
        vmax(m0, a0); vmax(m1, a1); vmax(m2, a2); vmax(m3, a3);
    }
    for (; k < w; ++k) {
        float4 a = base[(size_t)k * D4];
        vmax(m0, a);
    }
    vmax(m0, m1); vmax(m2, m3); vmax(m0, m2);
    float4 r = m0;
    ((float4*)g_rep)[(size_t)s * D4 + c] = r;

    // ---- partial logits for this span (identical math/order to R1) ----
    int d = ((s < NA) ? 0 : D) + c * 4;

    float acc[NK];
    #pragma unroll
    for (int q = 0; q < 2; ++q)
        acc[q] = r.x*Wv[(d+0)*2+q] + r.y*Wv[(d+1)*2+q]
               + r.z*Wv[(d+2)*2+q] + r.w*Wv[(d+3)*2+q];
    #pragma unroll
    for (int q = 0; q < NCAT; ++q)
        acc[2+q] = r.x*Wc[(d+0)*NCAT+q] + r.y*Wc[(d+1)*NCAT+q]
                 + r.z*Wc[(d+2)*NCAT+q] + r.w*Wc[(d+3)*NCAT+q];
    #pragma unroll
    for (int q = 0; q < NPOL; ++q)
        acc[15+q] = r.x*Wp[(d+0)*NPOL+q] + r.y*Wp[(d+1)*NPOL+q]
                  + r.z*Wp[(d+2)*NPOL+q] + r.w*Wp[(d+3)*NPOL+q];

    #pragma unroll
    for (int q = 0; q < NK; ++q)
        #pragma unroll
        for (int off = 16; off > 0; off >>= 1)
            acc[q] += __shfl_xor_sync(0xFFFFFFFFu, acc[q], off);

    __shared__ float sred[6][NK];
    int warp = c >> 5;
    if ((c & 31) == 0) {
        #pragma unroll
        for (int q = 0; q < NK; ++q) sred[warp][q] = acc[q];
    }
    __syncthreads();
    if (c < NK) {
        float t = 0.f;
        #pragma unroll
        for (int wv = 0; wv < 6; ++wv) t += sred[wv][c];   // fixed order
        g_part[s * NK + c] = t;
    }
}

// ---------------------------------------------------------------------------
// Kernel B: per-pair mask + all small outputs (ids, cat, pol, mask).
// One thread per pair; also materializes g_mask for the streaming kernel.
// Tiny traffic (~5.5 MB).
// ---------------------------------------------------------------------------
__global__ void __launch_bounds__(256) tail_kernel(
    const float* __restrict__ bv,
    const float* __restrict__ bc,
    const float* __restrict__ bp,
    float* __restrict__ out)
{
    int p = blockIdx.x * 256 + threadIdx.x;
    if (p >= NP) return;
    int i = p >> 8, j = p & 255;

    const float* pa = g_part + i * NK;
    const float* po = g_part + (NA + j) * NK;

    bool m = (pa[0] + po[0] + bv[0]) > (pa[1] + po[1] + bv[1]);

    g_mask[p] = m ? 1.f : 0.f;
    out[OFF_AID + p] = m ? (float)i : -1.f;
    out[OFF_OID + p] = m ? (float)j : -1.f;
    out[OFF_MSK + p] = m ? 1.f : 0.f;
    #pragma unroll
    for (int t = 0; t < NCAT; ++t)
        out[OFF_CAT + (size_t)p * NCAT + t] = m ? (pa[2 + t] + po[2 + t] + bc[t]) : 0.f;
    #pragma unroll
    for (int t = 0; t < NPOL; ++t)
        out[OFF_POL + (size_t)p * NPOL + t] = m ? (pa[15 + t] + po[15 + t] + bp[t]) : 0.f;
}

// ---------------------------------------------------------------------------
// Kernel C: pure 403 MB streaming write of pair_reps. Grid-stride over a
// flat float4 index space -> perfectly coalesced linear stores. Mask applied
// by multiply (no divergence). __stcs keeps the hot 1.5 MB rep table + mask
// resident in L2 while the output streams through.
// ---------------------------------------------------------------------------
__global__ void __launch_bounds__(256) pair_kernel(float* __restrict__ out)
{
    const unsigned total = (unsigned)NP * (2 * D4);   // 25,165,824 float4
    unsigned stride = gridDim.x * blockDim.x;
    const float4* rep = (const float4*)g_rep;
    float4* o = (float4*)out;

    for (unsigned idx = blockIdx.x * blockDim.x + threadIdx.x;
         idx < total; idx += stride) {
        unsigned p = idx / (2 * D4);                  // const-div -> mul/shift
        unsigned c = idx - p * (2 * D4);              // 0..383
        unsigned i = p >> 8, j = p & 255u;

        float msk = g_mask[p];
        unsigned src = (c < D4) ? (i * D4 + c) : ((NA + j) * D4 + (c - D4));
        float4 v = rep[src];
        v.x *= msk; v.y *= msk; v.z *= msk; v.w *= msk;
        __stcs(&o[idx], v);
    }
}

// ---------------------------------------------------------------------------
extern "C" void kernel_launch(void* const* d_in, const int* in_sizes, int n_in,
                              void* d_out, int out_size)
{
    const float* word_rep = (const float*)d_in[0];
    const int*   aspects  = (const int*)  d_in[1];
    const int*   opinions = (const int*)  d_in[2];
    const float* W_valid  = (const float*)d_in[3];
    const float* b_valid  = (const float*)d_in[4];
    const float* W_cat    = (const float*)d_in[5];
    const float* b_cat    = (const float*)d_in[6];
    const float* W_pol    = (const float*)d_in[7];
    const float* b_pol    = (const float*)d_in[8];
    float* out = (float*)d_out;

    pool_part_kernel<<<NA + NO, 192>>>(word_rep, aspects, opinions,
                                       W_valid, W_cat, W_pol);
    tail_kernel<<<(NP + 255) / 256, 256>>>(b_valid, b_cat, b_pol, out);
    pair_kernel<<<148 * 16, 256>>>(out);
}

// round 4
// speedup vs baseline: 1.0848x; 1.0848x over previous
#include <cuda_runtime.h>

// Problem constants
#define S    8192
#define D    768
#define D4   (D/4)        // 192 float4 per row
#define NA   256
#define NO   256
#define NP   (NA*NO)      // 65536 pairs
#define NCAT 13
#define NPOL 3
#define NK   18           // 2 valid + 13 cat + 3 pol partials per span

// Output layout (flattened tuple, fp32)
#define OFF_AID ((size_t)NP * (2*D))
#define OFF_OID (OFF_AID + NP)
#define OFF_CAT (OFF_OID + NP)
#define OFF_POL (OFF_CAT + (size_t)NP*NCAT)
#define OFF_MSK (OFF_POL + (size_t)NP*NPOL)

// Scratch (allocation-free rule: device globals)
__device__ float g_rep[(NA+NO)*D];     // aspect rows [0,256), opinion rows [256,512)
__device__ float g_part[(NA+NO)*NK];   // per-span partial logits (18 each)

static __device__ __forceinline__ void vmax(float4& a, const float4 b) {
    a.x = fmaxf(a.x, b.x);
    a.y = fmaxf(a.y, b.y);
    a.z = fmaxf(a.z, b.z);
    a.w = fmaxf(a.w, b.w);
}

// ---------------------------------------------------------------------------
// Kernel A: span max-pool ONLY (low register count). One block per span,
// 192 threads = 1 float4 lane each. 4 independent max accumulators -> MLP=4;
// max is exactly associative so the result is bit-identical.
// ---------------------------------------------------------------------------
__global__ void __launch_bounds__(192) span_pool_kernel(
    const float* __restrict__ word_rep,
    const int*   __restrict__ aspects,
    const int*   __restrict__ opinions)
{
    int s = blockIdx.x;                       // 0..511
    const int* sp = (s < NA) ? (aspects + 2*s) : (opinions + 2*(s - NA));
    int head = sp[0];
    int w    = sp[1] - head;                  // 1..40
    int c = threadIdx.x;                      // float4 lane 0..191

    const float4* base = (const float4*)word_rep + (size_t)head * D4 + c;
    float4 m0 = base[0];
    float4 m1 = m0, m2 = m0, m3 = m0;         // duplicates are max-identity
    int k = 1;
    for (; k + 3 < w; k += 4) {
        float4 a0 = base[(size_t)(k+0) * D4];
        float4 a1 = base[(size_t)(k+1) * D4];
        float4 a2 = base[(size_t)(k+2) * D4];
        float4 a3 = base[(size_t)(k+3) * D4];
        vmax(m0, a0); vmax(m1, a1); vmax(m2, a2); vmax(m3, a3);
    }
    for (; k < w; ++k)
        vmax(m0, base[(size_t)k * D4]);
    vmax(m0, m1); vmax(m2, m3); vmax(m0, m2);
    ((float4*)g_rep)[(size_t)s * D4 + c] = m0;
}

// ---------------------------------------------------------------------------
// Kernel B: per-span partial logits (identical to R1 — deterministic order).
// ---------------------------------------------------------------------------
__global__ void __launch_bounds__(192) part_kernel(
    const float* __restrict__ Wv,   // (2D, 2)   row-major
    const float* __restrict__ Wc,   // (2D, 13)
    const float* __restrict__ Wp)   // (2D, 3)
{
    int s = blockIdx.x;                       // 0..511
    int rowoff = (s < NA) ? 0 : D;
    int tid = threadIdx.x;                    // 0..191

    float4 r = ((const float4*)g_rep)[(size_t)s * D4 + tid];
    int d = rowoff + tid * 4;

    float acc[NK];
    #pragma unroll
    for (int c = 0; c < 2; ++c)
        acc[c] = r.x*Wv[(d+0)*2+c] + r.y*Wv[(d+1)*2+c]
               + r.z*Wv[(d+2)*2+c] + r.w*Wv[(d+3)*2+c];
    #pragma unroll
    for (int c = 0; c < NCAT; ++c)
        acc[2+c] = r.x*Wc[(d+0)*NCAT+c] + r.y*Wc[(d+1)*NCAT+c]
                 + r.z*Wc[(d+2)*NCAT+c] + r.w*Wc[(d+3)*NCAT+c];
    #pragma unroll
    for (int c = 0; c < NPOL; ++c)
        acc[15+c] = r.x*Wp[(d+0)*NPOL+c] + r.y*Wp[(d+1)*NPOL+c]
                  + r.z*Wp[(d+2)*NPOL+c] + r.w*Wp[(d+3)*NPOL+c];

    #pragma unroll
    for (int k = 0; k < NK; ++k)
        #pragma unroll
        for (int off = 16; off > 0; off >>= 1)
            acc[k] += __shfl_xor_sync(0xFFFFFFFFu, acc[k], off);

    __shared__ float sred[6][NK];
    int warp = tid >> 5;
    if ((tid & 31) == 0) {
        #pragma unroll
        for (int k = 0; k < NK; ++k) sred[warp][k] = acc[k];
    }
    __syncthreads();
    if (tid < NK) {
        float t = 0.f;
        #pragma unroll
        for (int w = 0; w < 6; ++w) t += sred[w][tid];   // fixed order
        g_part[s * NK + tid] = t;
    }
}

// ---------------------------------------------------------------------------
// Kernel C: identical to R1's pair kernel (best measured: ~63us for the
// 403 MB stream). One block per pair, 128 threads, __stcs streaming stores.
// ---------------------------------------------------------------------------
__global__ void __launch_bounds__(128) pair_kernel(
    const float* __restrict__ bv,
    const float* __restrict__ bc,
    const float* __restrict__ bp,
    float* __restrict__ out)
{
    int p = blockIdx.x;
    int i = p >> 8;            // aspect id
    int j = p & 255;           // opinion id

    const float* pa = g_part + i * NK;
    const float* po = g_part + (NA + j) * NK;

    float v0 = pa[0] + po[0] + bv[0];
    float v1 = pa[1] + po[1] + bv[1];
    bool m = v0 > v1;

    int t = threadIdx.x;
    const float4* ar = ((const float4*)g_rep) + (size_t)i        * D4;
    const float4* op = ((const float4*)g_rep) + (size_t)(NA + j) * D4;
    float4* outp = ((float4*)out) + (size_t)p * (2 * D4);

    const float4 z4 = make_float4(0.f, 0.f, 0.f, 0.f);
    #pragma unroll
    for (int it = 0; it < 3; ++it) {
        int c = t + it * 128;                // 0..383
        float4 v = z4;
        if (m) v = (c < D4) ? ar[c] : op[c - D4];
        __stcs(&outp[c], v);
    }

    if (t < NCAT)
        out[OFF_CAT + (size_t)p * NCAT + t] = m ? (pa[2 + t] + po[2 + t] + bc[t]) : 0.f;
    if (t >= 32 && t < 32 + NPOL) {
        int k = t - 32;
        out[OFF_POL + (size_t)p * NPOL + k] = m ? (pa[15 + k] + po[15 + k] + bp[k]) : 0.f;
    }
    if (t == 64) {
        out[OFF_AID + p] = m ? (float)i : -1.f;
        out[OFF_OID + p] = m ? (float)j : -1.f;
        out[OFF_MSK + p] = m ? 1.f : 0.f;
    }
}

// ---------------------------------------------------------------------------
extern "C" void kernel_launch(void* const* d_in, const int* in_sizes, int n_in,
                              void* d_out, int out_size)
{
    const float* word_rep = (const float*)d_in[0];   // (S, D)
    const int*   aspects  = (const int*)  d_in[1];   // (NA, 2)
    const int*   opinions = (const int*)  d_in[2];   // (NO, 2)
    const float* W_valid  = (const float*)d_in[3];   // (2D, 2)
    const float* b_valid  = (const float*)d_in[4];   // (2,)
    const float* W_cat    = (const float*)d_in[5];   // (2D, 13)
    const float* b_cat    = (const float*)d_in[6];   // (13,)
    const float* W_pol    = (const float*)d_in[7];   // (2D, 3)
    const float* b_pol    = (const float*)d_in[8];   // (3,)
    float* out = (float*)d_out;

    span_pool_kernel<<<NA + NO, 192>>>(word_rep, aspects, opinions);
    part_kernel     <<<NA + NO, 192>>>(W_valid, W_cat, W_pol);
    pair_kernel     <<<NP, 128>>>(b_valid, b_cat, b_pol, out);
}